// round 17
// baseline (speedup 1.0000x reference)
#include <cuda_runtime.h>
#include <cuda_bf16.h>
#include <math.h>
#include <float.h>
#include <stdint.h>

// ---------------------------------------------------------------------------
// Connectivity3D: fused PointNet (6->64->128->256 + BN + maxpool) on tensor
// cores using 3-pass bf16-split m16n8k16 mma.sync, then the algebraically-
// collapsed GCN/edge-MLP head (constant per object).
// R17: W3 hi/lo interleaved as uint2 (stage-3 B: 16 LDS.32 -> 8 LDS.64 per kt,
// conflict-free); whole post-pointnet tail fused into ONE kernel (4 obj/block).
// Arithmetic identical to R16: rel_err must stay 3.409998e-06 exactly.
// ---------------------------------------------------------------------------

#define PARTS 8192
#define PPTS  512
#define NOBJ  512
#define TP    64
#define NIT   (PPTS / TP)   // 8
#define THREADS 512

#define LDW2W 136   // prefolded W2 packed words (register-cached fragments)
#define LDW3P 260   // W3 interleaved uint2 leading dim (260 % 16 == 4 -> LDS.64 clean)
#define LDH1W 36    // 64 rows x 36 ( 36 % 32 == 4 -> ldmatrix conflict-free)
#define LDH2W 68    // 64 rows x 68 ( 68 % 32 == 4)

// scratch (device globals: no allocations allowed)
__device__ float    g_feat[PARTS * 256];
__device__ float    g_wc1s[256 * 256];
__device__ unsigned g_w2h[32 * LDW2W];
__device__ unsigned g_w2l[32 * LDW2W];
__device__ unsigned g_w3p[64 * LDW3P * 2];   // interleaved {hi, lo} words
__device__ float    g_w1f[6 * 64];
__device__ float    g_b1f[64];
__device__ float    g_b2f[128];
__device__ float    g_b3f[256];

// ---- shared layout (32-bit words) ----
#define OFF_W3P 0
#define OFF_H1H (OFF_W3P + 64 * LDW3P * 2)  // 33280
#define OFF_H1L (OFF_H1H + 64 * LDH1W)      // 35584
#define OFF_H2H (OFF_H1L + 64 * LDH1W)      // 37888
#define OFF_H2L (OFF_H2H + 64 * LDH2W)      // 42240
#define OFF_PTS (OFF_H2L + 64 * LDH2W)      // 46592
#define OFF_RED (OFF_PTS + TP * 6)          // 46976
#define SMEM_WORDS (OFF_RED + 512)          // 47488
#define SMEM_BYTES (SMEM_WORDS * 4)         // 189952 B

__device__ __forceinline__ void bfsplit1(float x, __nv_bfloat16& h, __nv_bfloat16& l) {
    h = __float2bfloat16_rn(x);
    l = __float2bfloat16_rn(x - __bfloat162float(h));
}
__device__ __forceinline__ void pack2(float x0, float x1, unsigned& hi, unsigned& lo) {
    __nv_bfloat16 h0, l0, h1, l1;
    bfsplit1(x0, h0, l0);
    bfsplit1(x1, h1, l1);
    __nv_bfloat162 hp = __halves2bfloat162(h0, h1);   // .x = low 16b = even k
    __nv_bfloat162 lp = __halves2bfloat162(l0, l1);
    hi = *reinterpret_cast<unsigned*>(&hp);
    lo = *reinterpret_cast<unsigned*>(&lp);
}
__device__ __forceinline__ void mma16(float c[4], const unsigned a[4], const unsigned b[2]) {
    asm volatile("mma.sync.aligned.m16n8k16.row.col.f32.bf16.bf16.f32 "
                 "{%0,%1,%2,%3}, {%4,%5,%6,%7}, {%8,%9}, {%0,%1,%2,%3};"
                 : "+f"(c[0]), "+f"(c[1]), "+f"(c[2]), "+f"(c[3])
                 : "r"(a[0]), "r"(a[1]), "r"(a[2]), "r"(a[3]), "r"(b[0]), "r"(b[1]));
}
__device__ __forceinline__ void mma3(float c[4],
                                     const unsigned ah[4], const unsigned al[4],
                                     const unsigned bh[2], const unsigned bl[2]) {
    mma16(c, ah, bh);
    mma16(c, ah, bl);
    mma16(c, al, bh);
}
__device__ __forceinline__ uint32_t smem_u32(const void* p) {
    uint32_t a;
    asm("{ .reg .u64 t; cvta.to.shared.u64 t, %1; cvt.u32.u64 %0, t; }" : "=r"(a) : "l"(p));
    return a;
}
__device__ __forceinline__ void ldsm_x4(unsigned r[4], uint32_t addr) {
    asm volatile("ldmatrix.sync.aligned.m8n8.x4.shared.b16 {%0,%1,%2,%3}, [%4];"
                 : "=r"(r[0]), "=r"(r[1]), "=r"(r[2]), "=r"(r[3]) : "r"(addr));
}

// ---------------------------------------------------------------------------
// Prep kernels (launches 1-3; pointnet is launch #4 for ncu)
// ---------------------------------------------------------------------------
__global__ void prep_misc_kernel(const float* __restrict__ Wc1,
                                 const float* __restrict__ W1, const float* __restrict__ b1,
                                 const float* __restrict__ g1, const float* __restrict__ bt1,
                                 const float* __restrict__ b2, const float* __restrict__ g2,
                                 const float* __restrict__ bt2,
                                 const float* __restrict__ b3, const float* __restrict__ g3,
                                 const float* __restrict__ bt3)
{
    const int i = blockIdx.x * 256 + threadIdx.x;
    g_wc1s[i] = Wc1[i] + Wc1[256 * 256 + i];
    if (blockIdx.x == 0) {
        const int t = threadIdx.x;
        g_w1f[t] = W1[t] * g1[t & 63];
        if (t < 128) g_w1f[t + 256] = W1[t + 256] * g1[t & 63];
        if (t < 64)  g_b1f[t] = b1[t] * g1[t] + bt1[t];
        if (t < 128) g_b2f[t] = b2[t] * g2[t] + bt2[t];
        g_b3f[t] = b3[t] * g3[t] + bt3[t];
    }
}

__global__ void prep_w2_kernel(const float* __restrict__ W2, const float* __restrict__ g2)
{
    const int i = blockIdx.x * 256 + threadIdx.x;   // 8192
    const int k = i >> 7, c = i & 127;
    float v = W2[i] * __ldg(&g2[c]);
    __nv_bfloat16 h, l;
    bfsplit1(v, h, l);
    const int bi = ((k >> 1) * LDW2W + c) * 2 + (k & 1);
    reinterpret_cast<__nv_bfloat16*>(g_w2h)[bi] = h;
    reinterpret_cast<__nv_bfloat16*>(g_w2l)[bi] = l;
}

// W3 -> interleaved {hi word, lo word} per (kp, col)
__global__ void prep_w3_kernel(const float* __restrict__ W3, const float* __restrict__ g3)
{
    const int i = blockIdx.x * 256 + threadIdx.x;   // 32768
    const int k = i >> 8, c = i & 255;
    float v = W3[i] * __ldg(&g3[c]);
    __nv_bfloat16 h, l;
    bfsplit1(v, h, l);
    const int slot = ((k >> 1) * LDW3P + c) * 4;    // bf16 index base of uint2
    __nv_bfloat16* p = reinterpret_cast<__nv_bfloat16*>(g_w3p);
    p[slot + (k & 1)]     = h;
    p[slot + 2 + (k & 1)] = l;
}

// ---------------------------------------------------------------------------
// Kernel A: one block (512 thr = 16 warps) per part; 64-point tiles,
// software-pipelined (pts(t+1) under stage-2 drain, stage-1(t+1) under
// stage-3 drain), 2 barriers/tile, ldmatrix A frags, uint2 B frags.
// ---------------------------------------------------------------------------
__global__ __launch_bounds__(THREADS, 1)
void pointnet_mma_kernel(const float* __restrict__ pcls)
{
    extern __shared__ unsigned smw[];
    uint2*    sW3p = reinterpret_cast<uint2*>(smw + OFF_W3P);
    unsigned* sH1h = smw + OFF_H1H;
    unsigned* sH1l = smw + OFF_H1L;
    unsigned* sH2h = smw + OFF_H2H;
    unsigned* sH2l = smw + OFF_H2L;
    float* sPt  = reinterpret_cast<float*>(smw + OFF_PTS);
    float* sRed = reinterpret_cast<float*>(smw + OFF_RED);
    __nv_bfloat16* sH1h_b = reinterpret_cast<__nv_bfloat16*>(sH1h);
    __nv_bfloat16* sH1l_b = reinterpret_cast<__nv_bfloat16*>(sH1l);

    const int tid  = threadIdx.x;
    const int w    = tid >> 5;        // 0..15
    const int lane = tid & 31;
    const int g    = lane >> 2;       // 0..7
    const int tg   = lane & 3;        // 0..3
    const int part = blockIdx.x;

    // ---- prologue: copy prefolded interleaved W3 into smem, uint4 ----
    {
        const uint4* s3 = reinterpret_cast<const uint4*>(g_w3p);
        uint4* d3 = reinterpret_cast<uint4*>(smw + OFF_W3P);
        #pragma unroll 4
        for (int i = tid; i < (64 * LDW3P * 2) / 4; i += THREADS) d3[i] = s3[i];
    }

    // ---- per-thread constants ----
    const int c1 = tid & 63;
    const int pg = tid >> 6;          // 0..7 -> 8 points each
    float w1r[6];
    #pragma unroll
    for (int d = 0; d < 6; d++) w1r[d] = __ldg(&g_w1f[d * 64 + c1]);
    const float b1f = __ldg(&g_b1f[c1]);

    const int mp2 = (w & 1) * 32;     // stage-2 rows (2 m-tiles of 16)
    const int nb2 = (w >> 1) * 16;    // stage-2 cols (2 n-tiles of 8)
    const int mh3 = (w & 1) * 32;     // stage-3 rows
    const int mhalf = w & 1;
    const int nb3 = (w >> 1) * 32;    // stage-3 cols (4 n-tiles of 8)

    // ldmatrix lane-address bases (constant across tiles; +32 B per kt)
    const int lrow = lane & 15;
    const int lkof = (lane & 16) ? 4 : 0;
    uint32_t a2b[2][2], a3b[2][2];    // [mt][hi/lo]
    {
        const uint32_t h1h = smem_u32(sH1h), h1l = smem_u32(sH1l);
        const uint32_t h2h = smem_u32(sH2h), h2l = smem_u32(sH2l);
        #pragma unroll
        for (int mt = 0; mt < 2; mt++) {
            const uint32_t o1 = 4u * ((mp2 + mt * 16 + lrow) * LDH1W + lkof);
            const uint32_t o2 = 4u * ((mh3 + mt * 16 + lrow) * LDH2W + lkof);
            a2b[mt][0] = h1h + o1; a2b[mt][1] = h1l + o1;
            a3b[mt][0] = h2h + o2; a3b[mt][1] = h2l + o2;
        }
    }

    // stage-2 B fragments: register-cached once from prefolded gmem
    unsigned b2r[4][2][2][2];         // [kt][nt][hi/lo][reg]
    #pragma unroll
    for (int kt = 0; kt < 4; kt++)
        #pragma unroll
        for (int nt = 0; nt < 2; nt++) {
            const int o = (kt * 8 + tg) * LDW2W + nb2 + nt * 8 + g;
            b2r[kt][nt][0][0] = __ldg(&g_w2h[o]);
            b2r[kt][nt][0][1] = __ldg(&g_w2h[o + 4 * LDW2W]);
            b2r[kt][nt][1][0] = __ldg(&g_w2l[o]);
            b2r[kt][nt][1][1] = __ldg(&g_w2l[o + 4 * LDW2W]);
        }
    float bb[2][2];
    #pragma unroll
    for (int nt = 0; nt < 2; nt++) {
        const int n = nb2 + nt * 8 + 2 * tg;
        bb[nt][0] = __ldg(&g_b2f[n]);
        bb[nt][1] = __ldg(&g_b2f[n + 1]);
    }

    float run_e[4], run_o[4];
    #pragma unroll
    for (int nt = 0; nt < 4; nt++) { run_e[nt] = -FLT_MAX; run_o[nt] = -FLT_MAX; }

    const float* pbase = pcls + (size_t)part * (PPTS * 6);

    // ---- prologue of pipeline: pts(0) + stage1(0) ----
    if (tid < TP * 6) sPt[tid] = pbase[tid];
    __syncthreads();
    #pragma unroll
    for (int r = 0; r < 8; r++) {
        const int p = pg * 8 + r;
        const float* pt = &sPt[p * 6];
        float a = b1f + pt[0]*w1r[0] + pt[1]*w1r[1] + pt[2]*w1r[2]
                      + pt[3]*w1r[3] + pt[4]*w1r[4] + pt[5]*w1r[5];
        a = fmaxf(a, 0.f);
        __nv_bfloat16 h, l;
        bfsplit1(a, h, l);
        const int bi = p * (LDH1W * 2) + c1;
        sH1h_b[bi] = h;
        sH1l_b[bi] = l;
    }
    __syncthreads();

    for (int t = 0; t < NIT; t++) {
        // ======== stage 2 (bf16x3 mma.sync): 64 x 128 ========
        float c2[2][2][4];
        #pragma unroll
        for (int mt = 0; mt < 2; mt++)
            #pragma unroll
            for (int nt = 0; nt < 2; nt++)
                #pragma unroll
                for (int j = 0; j < 4; j++) c2[mt][nt][j] = 0.f;

        #pragma unroll
        for (int kt = 0; kt < 4; kt++) {
            unsigned ah[2][4], al[2][4];
            ldsm_x4(ah[0], a2b[0][0] + kt * 32);
            ldsm_x4(al[0], a2b[0][1] + kt * 32);
            ldsm_x4(ah[1], a2b[1][0] + kt * 32);
            ldsm_x4(al[1], a2b[1][1] + kt * 32);
            #pragma unroll
            for (int nt = 0; nt < 2; nt++) {
                mma3(c2[0][nt], ah[0], al[0], b2r[kt][nt][0], b2r[kt][nt][1]);
                mma3(c2[1][nt], ah[1], al[1], b2r[kt][nt][0], b2r[kt][nt][1]);
            }
        }

        // ---- shadow: pts(t+1) global load (hides stage-2 pipe drain) ----
        float ptv = 0.f;
        const bool havep = (t + 1 < NIT) && (tid < TP * 6);
        if (havep) ptv = pbase[(t + 1) * TP * 6 + tid];

        // ---- stage-2 epilogue: bias+relu, split, store H2 ----
        #pragma unroll
        for (int mt = 0; mt < 2; mt++)
            #pragma unroll
            for (int nt = 0; nt < 2; nt++) {
                float v0 = fmaxf(c2[mt][nt][0] + bb[nt][0], 0.f);
                float v1 = fmaxf(c2[mt][nt][1] + bb[nt][1], 0.f);
                float v2 = fmaxf(c2[mt][nt][2] + bb[nt][0], 0.f);
                float v3 = fmaxf(c2[mt][nt][3] + bb[nt][1], 0.f);
                unsigned h0, l0, h1, l1;
                pack2(v0, v1, h0, l0);
                pack2(v2, v3, h1, l1);
                const int wcol = (nb2 >> 1) + nt * 4 + tg;
                const int r0 = mp2 + mt * 16 + g;
                sH2h[r0 * LDH2W + wcol]       = h0;
                sH2l[r0 * LDH2W + wcol]       = l0;
                sH2h[(r0 + 8) * LDH2W + wcol] = h1;
                sH2l[(r0 + 8) * LDH2W + wcol] = l1;
            }
        if (havep) sPt[tid] = ptv;
        __syncthreads();

        // ======== stage 3 (bf16x3 mma.sync): 64 x 256 ========
        float d[2][4][4];
        #pragma unroll
        for (int mt = 0; mt < 2; mt++)
            #pragma unroll
            for (int nt = 0; nt < 4; nt++)
                #pragma unroll
                for (int j = 0; j < 4; j++) d[mt][nt][j] = 0.f;

        #pragma unroll
        for (int kt = 0; kt < 8; kt++) {
            unsigned ah[2][4], al[2][4];
            ldsm_x4(ah[0], a3b[0][0] + kt * 32);
            ldsm_x4(al[0], a3b[0][1] + kt * 32);
            ldsm_x4(ah[1], a3b[1][0] + kt * 32);
            ldsm_x4(al[1], a3b[1][1] + kt * 32);
            const uint2* qbase = sW3p + (kt * 8 + tg) * LDW3P + nb3 + g;
            #pragma unroll
            for (int nt = 0; nt < 4; nt++) {
                const uint2 v0 = qbase[nt * 8];
                const uint2 v1 = qbase[nt * 8 + 4 * LDW3P];
                unsigned bh[2] = { v0.x, v1.x };
                unsigned bl[2] = { v0.y, v1.y };
                mma3(d[0][nt], ah[0], al[0], bh, bl);
                mma3(d[1][nt], ah[1], al[1], bh, bl);
            }
        }

        // ---- shadow: stage-1(t+1) (hides stage-3 pipe drain) ----
        if (t + 1 < NIT) {
            #pragma unroll
            for (int r = 0; r < 8; r++) {
                const int p = pg * 8 + r;
                const float* pt = &sPt[p * 6];
                float a = b1f + pt[0]*w1r[0] + pt[1]*w1r[1] + pt[2]*w1r[2]
                              + pt[3]*w1r[3] + pt[4]*w1r[4] + pt[5]*w1r[5];
                a = fmaxf(a, 0.f);
                __nv_bfloat16 h, l;
                bfsplit1(a, h, l);
                const int bi = p * (LDH1W * 2) + c1;
                sH1h_b[bi] = h;
                sH1l_b[bi] = l;
            }
        }

        // ---- stage-3 accumulator reads: running max ----
        #pragma unroll
        for (int nt = 0; nt < 4; nt++) {
            run_e[nt] = fmaxf(run_e[nt],
                        fmaxf(fmaxf(d[0][nt][0], d[0][nt][2]),
                              fmaxf(d[1][nt][0], d[1][nt][2])));
            run_o[nt] = fmaxf(run_o[nt],
                        fmaxf(fmaxf(d[0][nt][1], d[0][nt][3]),
                              fmaxf(d[1][nt][1], d[1][nt][3])));
        }
        __syncthreads();
    }

    // ---- warp-level max over point rows -> sRed; combine the 2 m-halves ----
    #pragma unroll
    for (int nt = 0; nt < 4; nt++) {
        float e = run_e[nt], o = run_o[nt];
        #pragma unroll
        for (int off = 4; off <= 16; off <<= 1) {
            e = fmaxf(e, __shfl_xor_sync(0xffffffffu, e, off));
            o = fmaxf(o, __shfl_xor_sync(0xffffffffu, o, off));
        }
        if (g == 0) {
            const int ce = nb3 + nt * 8 + 2 * tg;
            sRed[mhalf * 256 + ce]     = e;
            sRed[mhalf * 256 + ce + 1] = o;
        }
    }
    __syncthreads();
    if (tid < 256) {
        const float v = fmaxf(sRed[tid], sRed[256 + tid]) + __ldg(&g_b3f[tid]);
        g_feat[part * 256 + tid] = v;
    }
}

// ---------------------------------------------------------------------------
// Fused tail: fmean + 5-layer chain + head dot + tanh + scatter.
// 4 objects per block, grid 128. Row-wise exact (per-object independence).
// Reduction orders replicate the previous separate kernels bit-for-bit.
// ---------------------------------------------------------------------------
#define HR 4
__global__ __launch_bounds__(256)
void head_fused_kernel(const float* __restrict__ We,  const float* __restrict__ be,
                       const float* __restrict__ Wg1, const float* __restrict__ bg1,
                       const float* __restrict__ Wg2, const float* __restrict__ bg2,
                       const float* __restrict__ bc1,
                       const float* __restrict__ Wc2, const float* __restrict__ bc2,
                       const float* __restrict__ Wc3, const float* __restrict__ bc3,
                       float* __restrict__ out)
{
    __shared__ float sA[HR][256];
    __shared__ float sB[HR][256];
    __shared__ float sS[HR];
    const int r0  = blockIdx.x * HR;
    const int tid = threadIdx.x;

    // fmean
    #pragma unroll
    for (int r = 0; r < HR; r++) {
        float s = 0.f;
        #pragma unroll
        for (int k = 0; k < 16; k++) s += g_feat[((r0 + r) * 16 + k) * 256 + tid];
        sA[r][tid] = s * (1.f / 16.f);
    }
    __syncthreads();

    // layers: src -> dst
    {   // L1: emb = fmean @ We + be
        float acc[HR] = {0.f, 0.f, 0.f, 0.f};
        #pragma unroll 8
        for (int k = 0; k < 256; k++) {
            const float wv = We[k * 256 + tid];
            #pragma unroll
            for (int r = 0; r < HR; r++) acc[r] += sA[r][k] * wv;
        }
        const float b = be[tid];
        #pragma unroll
        for (int r = 0; r < HR; r++) sB[r][tid] = acc[r] + b;
        __syncthreads();
    }
    {   // L2: relu(@Wg1 + bg1)
        float acc[HR] = {0.f, 0.f, 0.f, 0.f};
        #pragma unroll 8
        for (int k = 0; k < 256; k++) {
            const float wv = Wg1[k * 256 + tid];
            #pragma unroll
            for (int r = 0; r < HR; r++) acc[r] += sB[r][k] * wv;
        }
        const float b = bg1[tid];
        #pragma unroll
        for (int r = 0; r < HR; r++) sA[r][tid] = fmaxf(acc[r] + b, 0.f);
        __syncthreads();
    }
    {   // L3: @Wg2 + bg2
        float acc[HR] = {0.f, 0.f, 0.f, 0.f};
        #pragma unroll 8
        for (int k = 0; k < 256; k++) {
            const float wv = Wg2[k * 256 + tid];
            #pragma unroll
            for (int r = 0; r < HR; r++) acc[r] += sA[r][k] * wv;
        }
        const float b = bg2[tid];
        #pragma unroll
        for (int r = 0; r < HR; r++) sB[r][tid] = acc[r] + b;
        __syncthreads();
    }
    {   // L4: relu(@wc1s + bc1)
        float acc[HR] = {0.f, 0.f, 0.f, 0.f};
        #pragma unroll 8
        for (int k = 0; k < 256; k++) {
            const float wv = g_wc1s[k * 256 + tid];
            #pragma unroll
            for (int r = 0; r < HR; r++) acc[r] += sB[r][k] * wv;
        }
        const float b = bc1[tid];
        #pragma unroll
        for (int r = 0; r < HR; r++) sA[r][tid] = fmaxf(acc[r] + b, 0.f);
        __syncthreads();
    }
    {   // L5: relu(@Wc2 + bc2)
        float acc[HR] = {0.f, 0.f, 0.f, 0.f};
        #pragma unroll 8
        for (int k = 0; k < 256; k++) {
            const float wv = Wc2[k * 256 + tid];
            #pragma unroll
            for (int r = 0; r < HR; r++) acc[r] += sA[r][k] * wv;
        }
        const float b = bc2[tid];
        #pragma unroll
        for (int r = 0; r < HR; r++) sB[r][tid] = fmaxf(acc[r] + b, 0.f);
        __syncthreads();
    }

    // head: warp r does row r, lane-strided dot (matches old head_kernel order)
    const int w    = tid >> 5;
    const int lane = tid & 31;
    if (w < HR) {
        float a = 0.f;
        #pragma unroll
        for (int k = lane; k < 256; k += 32) a += sB[w][k] * Wc3[k];
        #pragma unroll
        for (int off = 16; off; off >>= 1) a += __shfl_xor_sync(0xffffffffu, a, off);
        if (lane == 0) sS[w] = tanhf(a + bc3[0]);
    }
    __syncthreads();

    // scatter: out[o][i][j] = (i==j) ? 0 : s[o]
    const int i = tid >> 4, j = tid & 15;
    #pragma unroll
    for (int r = 0; r < HR; r++)
        out[(r0 + r) * 256 + tid] = (i == j) ? 0.f : sS[r];
}

// ---------------------------------------------------------------------------
extern "C" void kernel_launch(void* const* d_in, const int* in_sizes, int n_in,
                              void* d_out, int out_size)
{
    (void)in_sizes; (void)n_in; (void)out_size;
    const float* pcls = (const float*)d_in[0];
    const float* W1 = (const float*)d_in[1];  const float* b1 = (const float*)d_in[2];
    const float* g1 = (const float*)d_in[3];  const float* bt1 = (const float*)d_in[4];
    const float* W2 = (const float*)d_in[5];  const float* b2 = (const float*)d_in[6];
    const float* g2 = (const float*)d_in[7];  const float* bt2 = (const float*)d_in[8];
    const float* W3 = (const float*)d_in[9];  const float* b3 = (const float*)d_in[10];
    const float* g3 = (const float*)d_in[11]; const float* bt3 = (const float*)d_in[12];
    const float* We = (const float*)d_in[13]; const float* be = (const float*)d_in[14];
    const float* Wg1 = (const float*)d_in[15]; const float* bg1 = (const float*)d_in[16];
    const float* Wg2 = (const float*)d_in[17]; const float* bg2 = (const float*)d_in[18];
    const float* Wc1 = (const float*)d_in[19]; const float* bc1 = (const float*)d_in[20];
    const float* Wc2 = (const float*)d_in[21]; const float* bc2 = (const float*)d_in[22];
    const float* Wc3 = (const float*)d_in[23]; const float* bc3 = (const float*)d_in[24];

    cudaFuncSetAttribute(pointnet_mma_kernel,
                         cudaFuncAttributeMaxDynamicSharedMemorySize, SMEM_BYTES);

    // launches 1-3: one-shot weight prep (pointnet = launch #4 for ncu)
    prep_misc_kernel<<<256, 256>>>(Wc1, W1, b1, g1, bt1, b2, g2, bt2, b3, g3, bt3);
    prep_w2_kernel<<<32, 256>>>(W2, g2);
    prep_w3_kernel<<<128, 256>>>(W3, g3);

    pointnet_mma_kernel<<<PARTS, THREADS, SMEM_BYTES>>>(pcls);

    head_fused_kernel<<<NOBJ / HR, 256>>>(We, be, Wg1, bg1, Wg2, bg2,
                                          bc1, Wc2, bc2, Wc3, bc3,
                                          (float*)d_out);
}